// round 4
// baseline (speedup 1.0000x reference)
#include <cuda_runtime.h>
#include <cstdint>

#define LGRID 512
#define BATCH 32768
#define TPB   64
#define NBLK  (BATCH / TPB)   // 512 blocks, 32768 threads, 1024 warps

__global__ __launch_bounds__(TPB)
void ode_euler4_kernel(const float* __restrict__ s_grid,
                       const float* __restrict__ y0,
                       const float* __restrict__ w,
                       float* __restrict__ out) {
    __shared__ float sh_h[LGRID - 1];

    const int tid  = threadIdx.x;
    const int lane = tid & 31;

    for (int j = tid; j < LGRID - 1; j += TPB)
        sh_h[j] = s_grid[j + 1] - s_grid[j];
    __syncthreads();

    // lane layout: c = lane>>3 (component 0..3), q = lane&7 (trajectory quad)
    const int c = lane >> 3;
    const int q = lane & 7;

    // this thread: component c of trajectories j0 .. j0+3
    const int warp_g = (blockIdx.x * TPB + tid) >> 5;
    const int j0 = warp_g * 32 + q * 4;

    // per-component weights:
    //   dY = wa + wb*y + wc*y^2 + wd*p + we*p^2 + wf*p*y
    //      = (wa + wb*y + wc*y^2) + p*(wd + we*p + wf*y)
    // c=0: w0,w1,w2 and no cross terms
    // c>0: base = 3 + 6*(c-1)
    float wa, wb, wc_, wd, we, wf;
    if (c == 0) {
        wa = __ldg(w + 0); wb = __ldg(w + 1); wc_ = __ldg(w + 2);
        wd = 0.0f; we = 0.0f; wf = 0.0f;
    } else {
        const int base = 3 + 6 * (c - 1);
        wa  = __ldg(w + base + 0);
        wb  = __ldg(w + base + 1);
        wc_ = __ldg(w + base + 2);
        wd  = __ldg(w + base + 3);
        we  = __ldg(w + base + 4);
        wf  = __ldg(w + base + 5);
    }

    // load initial state: 4 consecutive trajectories, component c
    float4 yv = *(const float4*)(y0 + (size_t)c * BATCH + j0);
    float ya = yv.x, yb = yv.y, yc = yv.z, yd = yv.w;

    // emit y0
    __stcs((float4*)(out + (size_t)c * BATCH + j0), yv);

    #pragma unroll 2
    for (int i = 0; i < LGRID - 1; ++i) {
        const float h = sh_h[i];

        // cross term: previous component's value (same step), from lane-8.
        // lanes 0-7 (c=0) get their own value back; multiplied by 0 weights.
        const float pa = __shfl_up_sync(0xffffffffu, ya, 8);
        const float pb = __shfl_up_sync(0xffffffffu, yb, 8);
        const float pc = __shfl_up_sync(0xffffffffu, yc, 8);
        const float pd = __shfl_up_sync(0xffffffffu, yd, 8);

        // trajectory a
        {
            const float y2 = ya * ya;
            float t1 = fmaf(wb, ya, wa);  t1 = fmaf(wc_, y2, t1);
            float u  = fmaf(we, pa, wd);  u  = fmaf(wf, ya, u);
            const float d = fmaf(pa, u, t1);
            ya = fmaf(h, d, ya);
        }
        // trajectory b
        {
            const float y2 = yb * yb;
            float t1 = fmaf(wb, yb, wa);  t1 = fmaf(wc_, y2, t1);
            float u  = fmaf(we, pb, wd);  u  = fmaf(wf, yb, u);
            const float d = fmaf(pb, u, t1);
            yb = fmaf(h, d, yb);
        }
        // trajectory c
        {
            const float y2 = yc * yc;
            float t1 = fmaf(wb, yc, wa);  t1 = fmaf(wc_, y2, t1);
            float u  = fmaf(we, pc, wd);  u  = fmaf(wf, yc, u);
            const float d = fmaf(pc, u, t1);
            yc = fmaf(h, d, yc);
        }
        // trajectory d
        {
            const float y2 = yd * yd;
            float t1 = fmaf(wb, yd, wa);  t1 = fmaf(wc_, y2, t1);
            float u  = fmaf(we, pd, wd);  u  = fmaf(wf, yd, u);
            const float d = fmaf(pd, u, t1);
            yd = fmaf(h, d, yd);
        }

        // one STG.128: component plane c, 4 consecutive trajectories.
        // octet (8 lanes, same c) covers 128 contiguous bytes.
        float4 o; o.x = ya; o.y = yb; o.z = yc; o.w = yd;
        __stcs((float4*)(out + (size_t)(i + 1) * (4 * BATCH)
                             + (size_t)c * BATCH + j0), o);
    }
}

extern "C" void kernel_launch(void* const* d_in, const int* in_sizes, int n_in,
                              void* d_out, int out_size) {
    const float* s_grid = (const float*)d_in[0];
    const float* y0     = (const float*)d_in[1];
    const float* w      = (const float*)d_in[2];
    float* out          = (float*)d_out;

    ode_euler4_kernel<<<NBLK, TPB>>>(s_grid, y0, w, out);
}